// round 2
// baseline (speedup 1.0000x reference)
#include <cuda_runtime.h>
#include <cuda_bf16.h>
#include <cstdint>

// ============================================================================
// BcosGCNLayer: out[n,o] = lin*|lin| / (max(||z_n||,eps)*max(||w_o||,eps))
// lin = z @ W^T ; z [M,512] f32, W [512,512] f32, out [M,512] f32
// bf16 hi/lo split GEMM on mma.sync.m16n8k16 (family-portable; no tcgen05 —
// ptxas target here is compute_103 without the 'a' feature set).
// CTA 128x256, K-chunk 64, 2-stage cp.async pipeline, fused norm epilogue.
// ============================================================================

#define KDIM 512
#define NDIM 512
#define TM   128
#define TN   256
#define KC   64
#define NCHUNKS 8
#define NTHREADS 256

// SMEM layout (dynamic)
#define S_ZS   0          // 128 f32 inverse z-norms
#define S_WNI  512        // 256 f32 inverse w-norms
#define S_A    2048       // 2 stages x 32KB (fp32 A tile, 16B-XOR swizzle)
#define S_B    67584      // 2 stages x 64KB (bf16 hi 32KB + lo 32KB, SW128)
#define S_TOTAL 198656

__device__ __nv_bfloat16 g_w_hi[NDIM * KDIM];
__device__ __nv_bfloat16 g_w_lo[NDIM * KDIM];
__device__ float         g_wninv[NDIM];

// ---------------- helpers ----------------
__device__ __forceinline__ uint32_t smem_u32(const void* p) {
    uint32_t a;
    asm("{ .reg .u64 t; cvta.to.shared.u64 t, %1; cvt.u32.u64 %0, t; }"
        : "=r"(a) : "l"(p));
    return a;
}

__device__ __forceinline__ void mma_bf16(float d[4], const uint32_t a[4],
                                         const uint32_t b[2]) {
    asm volatile(
        "mma.sync.aligned.m16n8k16.row.col.f32.bf16.bf16.f32 "
        "{%0,%1,%2,%3}, {%4,%5,%6,%7}, {%8,%9}, {%0,%1,%2,%3};"
        : "+f"(d[0]), "+f"(d[1]), "+f"(d[2]), "+f"(d[3])
        : "r"(a[0]), "r"(a[1]), "r"(a[2]), "r"(a[3]),
          "r"(b[0]), "r"(b[1]));
}

__device__ __forceinline__ void ldsm_x4(uint32_t& r0, uint32_t& r1,
                                        uint32_t& r2, uint32_t& r3,
                                        uint32_t addr) {
    asm volatile(
        "ldmatrix.sync.aligned.m8n8.x4.shared.b16 {%0,%1,%2,%3}, [%4];"
        : "=r"(r0), "=r"(r1), "=r"(r2), "=r"(r3) : "r"(addr));
}

// split a float2 into bf16x2 hi and lo parts
__device__ __forceinline__ void split2(float2 v, uint32_t& hi, uint32_t& lo) {
    __nv_bfloat162 h = __floats2bfloat162_rn(v.x, v.y);
    float2 hf = __bfloat1622float2(h);
    __nv_bfloat162 l = __floats2bfloat162_rn(v.x - hf.x, v.y - hf.y);
    hi = *reinterpret_cast<uint32_t*>(&h);
    lo = *reinterpret_cast<uint32_t*>(&l);
}

__device__ __forceinline__ uint32_t pack_bf16x2(float a, float b) {
    __nv_bfloat162 t = __floats2bfloat162_rn(a, b);
    return *reinterpret_cast<uint32_t*>(&t);
}

// ---------------------------------------------------------------------------
// Kernel 1: weight prep — hi/lo split + inverse row norms
// ---------------------------------------------------------------------------
__global__ void prep_weight(const float* __restrict__ w) {
    int row = blockIdx.x;
    int t   = threadIdx.x;

    float4 v = reinterpret_cast<const float4*>(w)[row * 128 + t];
    float ssq = v.x * v.x + v.y * v.y + v.z * v.z + v.w * v.w;

    uint32_t h0, l0, h1, l1;
    split2(make_float2(v.x, v.y), h0, l0);
    split2(make_float2(v.z, v.w), h1, l1);

    *reinterpret_cast<uint2*>(&g_w_hi[row * KDIM + t * 4]) = make_uint2(h0, h1);
    *reinterpret_cast<uint2*>(&g_w_lo[row * KDIM + t * 4]) = make_uint2(l0, l1);

    #pragma unroll
    for (int off = 16; off > 0; off >>= 1)
        ssq += __shfl_xor_sync(0xFFFFFFFFu, ssq, off);

    __shared__ float ws[4];
    if ((t & 31) == 0) ws[t >> 5] = ssq;
    __syncthreads();
    if (t == 0) {
        float s = ws[0] + ws[1] + ws[2] + ws[3];
        g_wninv[row] = 1.0f / fmaxf(sqrtf(s), 1e-12f);
    }
}

// ---------------------------------------------------------------------------
// Kernel 2: fused bf16-split GEMM + bcos epilogue (mma.sync path)
// ---------------------------------------------------------------------------
__global__ void __launch_bounds__(NTHREADS, 1)
bcos_gemm(const float* __restrict__ z, float* __restrict__ out, int M) {
    extern __shared__ char smem[];
    uint32_t sb = smem_u32(smem);
    int tid = threadIdx.x;
    int wid = tid >> 5, lid = tid & 31;
    int mw = wid >> 2, nw = wid & 3;       // warp grid 2(m) x 4(n)
    int mbase = mw * 64, nbase = nw * 64;  // warp tile 64x64
    int g = lid >> 2, q = lid & 3;

    int tm = blockIdx.x >> 1, tn = blockIdx.x & 1;
    int m0 = tm * TM, n0 = tn * TN;

    // inverse weight norms for this N tile
    reinterpret_cast<float*>(smem + S_WNI)[tid] = g_wninv[n0 + tid];

    float acc[4][8][4];
    #pragma unroll
    for (int a = 0; a < 4; a++)
        #pragma unroll
        for (int b = 0; b < 8; b++)
            #pragma unroll
            for (int c = 0; c < 4; c++) acc[a][b][c] = 0.0f;
    float ssq = 0.0f;

    // ---- async copy of one K-chunk into stage s ----
    auto copyA = [&](int c, int s) {
        int k0 = c * KC;
        #pragma unroll
        for (int i = 0; i < 8; i++) {
            int id = tid + i * NTHREADS;          // 0..2047 (16B units)
            int row = id >> 4, c16 = id & 15;
            int grow = m0 + row;
            const float* src = z + (size_t)(grow < M ? grow : 0) * KDIM + k0 + c16 * 4;
            uint32_t dst = sb + S_A + s * 32768 + row * 256 + ((c16 ^ (row & 15)) << 4);
            int sz = (grow < M) ? 16 : 0;
            asm volatile("cp.async.cg.shared.global [%0], [%1], 16, %2;"
                         :: "r"(dst), "l"(src), "r"(sz));
        }
    };
    auto copyB = [&](int c, int s) {
        int k0 = c * KC;
        #pragma unroll
        for (int i = 0; i < 16; i++) {
            int id = tid + i * NTHREADS;          // 0..4095
            int part = id >> 11, rid = id & 2047;
            int row = rid >> 3, c16 = rid & 7;
            const __nv_bfloat16* base = part ? g_w_lo : g_w_hi;
            const __nv_bfloat16* src = base + (size_t)(n0 + row) * KDIM + k0 + c16 * 8;
            uint32_t dst = sb + S_B + s * 65536 + part * 32768
                         + row * 128 + ((c16 * 16) ^ ((row & 7) * 16));
            asm volatile("cp.async.cg.shared.global [%0], [%1], 16;"
                         :: "r"(dst), "l"(src));
        }
    };

    copyA(0, 0); copyB(0, 0);
    asm volatile("cp.async.commit_group;");
    copyA(1, 1); copyB(1, 1);
    asm volatile("cp.async.commit_group;");

    for (int c = 0; c < NCHUNKS; c++) {
        int s = c & 1;
        if (c < NCHUNKS - 1) asm volatile("cp.async.wait_group 1;");
        else                 asm volatile("cp.async.wait_group 0;");
        __syncthreads();

        // ---- row ssq pass (each thread owns half a row this chunk)
        {
            const uint4* As = reinterpret_cast<const uint4*>(smem + S_A + s * 32768);
            int row = tid >> 1, h = tid & 1;
            #pragma unroll
            for (int j = 0; j < 8; j++) {
                int c16 = h * 8 + j;
                uint4 v = As[row * 16 + (c16 ^ (row & 15))];
                float x0 = __uint_as_float(v.x), x1 = __uint_as_float(v.y);
                float x2 = __uint_as_float(v.z), x3 = __uint_as_float(v.w);
                ssq += x0 * x0 + x1 * x1 + x2 * x2 + x3 * x3;
            }
        }

        const char* Af = smem + S_A + s * 32768;
        uint32_t Bbase = sb + S_B + s * 65536;

        #pragma unroll
        for (int ks = 0; ks < 4; ks++) {
            int k16 = ks * 16;
            int kc0 = k16 + 2 * q;

            // ---- A fragments (fp32 smem -> bf16 hi/lo regs)
            uint32_t ahi[4][4], alo[4][4];
            #pragma unroll
            for (int mt = 0; mt < 4; mt++) {
                int r0 = mbase + mt * 16 + g;
                int r1 = r0 + 8;
                #define AOFF(rr, kk) ((rr) * 256 + ((((kk) >> 2) ^ ((rr) & 15)) << 4) + ((kk) & 3) * 4)
                float2 x0 = *reinterpret_cast<const float2*>(Af + AOFF(r0, kc0));
                float2 x1 = *reinterpret_cast<const float2*>(Af + AOFF(r1, kc0));
                float2 x2 = *reinterpret_cast<const float2*>(Af + AOFF(r0, kc0 + 8));
                float2 x3 = *reinterpret_cast<const float2*>(Af + AOFF(r1, kc0 + 8));
                split2(x0, ahi[mt][0], alo[mt][0]);
                split2(x1, ahi[mt][1], alo[mt][1]);
                split2(x2, ahi[mt][2], alo[mt][2]);
                split2(x3, ahi[mt][3], alo[mt][3]);
            }

            // ---- B fragments via ldmatrix.x4 (non-trans on [n][k] rows)
            uint32_t bhi[8][2], blo[8][2];
            int lt = lid >> 3, lr = lid & 7;
            #pragma unroll
            for (int jj = 0; jj < 4; jj++) {
                int j = jj * 2 + (lt >> 1);
                int kk = k16 + (lt & 1) * 8;
                int row = nbase + j * 8 + lr;
                uint32_t a0 = Bbase + row * 128 + ((kk * 2) ^ ((row & 7) * 16));
                ldsm_x4(bhi[jj * 2][0], bhi[jj * 2][1],
                        bhi[jj * 2 + 1][0], bhi[jj * 2 + 1][1], a0);
                ldsm_x4(blo[jj * 2][0], blo[jj * 2][1],
                        blo[jj * 2 + 1][0], blo[jj * 2 + 1][1], a0 + 32768);
            }

            // ---- 3-term split MMAs
            #pragma unroll
            for (int mt = 0; mt < 4; mt++)
                #pragma unroll
                for (int nt = 0; nt < 8; nt++) {
                    mma_bf16(acc[mt][nt], ahi[mt], bhi[nt]);
                    mma_bf16(acc[mt][nt], ahi[mt], blo[nt]);
                    mma_bf16(acc[mt][nt], alo[mt], bhi[nt]);
                }
        }

        __syncthreads();
        if (c + 2 < NCHUNKS) {
            copyA(c + 2, s); copyB(c + 2, s);
            asm volatile("cp.async.commit_group;");
        }
    }

    // ---- publish inverse z-norms
    ssq += __shfl_xor_sync(0xFFFFFFFFu, ssq, 1);
    if ((tid & 1) == 0)
        reinterpret_cast<float*>(smem + S_ZS)[tid >> 1] =
            1.0f / fmaxf(sqrtf(ssq), 1e-12f);
    __syncthreads();

    // ---- epilogue: out = v*|v| * invzn * invwn
    const float* zs  = reinterpret_cast<const float*>(smem + S_ZS);
    const float* wni = reinterpret_cast<const float*>(smem + S_WNI);

    #pragma unroll
    for (int mt = 0; mt < 4; mt++) {
        int r0 = mbase + mt * 16 + g;
        float iz0 = zs[r0], iz1 = zs[r0 + 8];
        int gr0 = m0 + r0;
        bool ok0 = (gr0 < M), ok1 = (gr0 + 8 < M);
        float* op0 = out + (size_t)gr0 * NDIM + n0;
        float* op1 = op0 + (size_t)8 * NDIM;
        #pragma unroll
        for (int nt = 0; nt < 8; nt++) {
            int cb = nbase + nt * 8 + 2 * q;
            float w0 = wni[cb], w1 = wni[cb + 1];
            if (ok0) {
                float v0 = acc[mt][nt][0], v1 = acc[mt][nt][1];
                float2 o;
                o.x = v0 * fabsf(v0) * iz0 * w0;
                o.y = v1 * fabsf(v1) * iz0 * w1;
                *reinterpret_cast<float2*>(op0 + cb) = o;
            }
            if (ok1) {
                float v2 = acc[mt][nt][2], v3 = acc[mt][nt][3];
                float2 o;
                o.x = v2 * fabsf(v2) * iz1 * w0;
                o.y = v3 * fabsf(v3) * iz1 * w1;
                *reinterpret_cast<float2*>(op1 + cb) = o;
            }
        }
    }
}

// ---------------------------------------------------------------------------
extern "C" void kernel_launch(void* const* d_in, const int* in_sizes, int n_in,
                              void* d_out, int out_size) {
    const float* z = (const float*)d_in[0];
    const float* w = (const float*)d_in[1];
    float* out = (float*)d_out;
    int M = in_sizes[0] / KDIM;

    cudaFuncSetAttribute(bcos_gemm,
                         cudaFuncAttributeMaxDynamicSharedMemorySize, S_TOTAL);

    prep_weight<<<NDIM, 128>>>(w);

    int tiles_m = (M + TM - 1) / TM;
    bcos_gemm<<<tiles_m * 2, NTHREADS, S_TOTAL>>>(z, out, M);
}

// round 3
// speedup vs baseline: 1.0727x; 1.0727x over previous
#include <cuda_runtime.h>
#include <cuda_bf16.h>
#include <cstdint>

// ============================================================================
// BcosGCNLayer: out[n,o] = lin*|lin| / (max(||z_n||,eps)*max(||w_o||,eps))
// lin = z @ W^T ; z [M,512] f32, W [512,512] f32, out [M,512] f32
// bf16 hi/lo split GEMM (3 MMAs: hh+hl+lh) on mma.sync.m16n8k16.
// CTA 128x256, K-chunk 64, 2-stage cp.async pipeline.
// R3: A converted to bf16 hi/lo SMEM once per chunk (fused ssq), A frags via
// ldmatrix; B frag loads halved to cut register pressure (was 255 regs+spill).
// ============================================================================

#define KDIM 512
#define NDIM 512
#define TM   128
#define TN   256
#define KC   64
#define NCHUNKS 8
#define NTHREADS 256

// SMEM layout (dynamic)
#define S_ZS    0            // 128 f32 inverse z-norms
#define S_WNI   512          // 256 f32 inverse w-norms
#define S_ABF   1536         // A bf16: hi 16KB @ +0, lo 16KB @ +16384
#define S_AF32  34304        // 2 stages x 32KB fp32 A tile
#define S_B     99840        // 2 stages x 64KB (bf16 hi 32KB + lo 32KB, SW128)
#define S_TOTAL 230912

__device__ __nv_bfloat16 g_w_hi[NDIM * KDIM];
__device__ __nv_bfloat16 g_w_lo[NDIM * KDIM];
__device__ float         g_wninv[NDIM];

// ---------------- helpers ----------------
__device__ __forceinline__ uint32_t smem_u32(const void* p) {
    uint32_t a;
    asm("{ .reg .u64 t; cvta.to.shared.u64 t, %1; cvt.u32.u64 %0, t; }"
        : "=r"(a) : "l"(p));
    return a;
}

__device__ __forceinline__ void mma_bf16(float d[4], const uint32_t a[4],
                                         const uint32_t b[2]) {
    asm volatile(
        "mma.sync.aligned.m16n8k16.row.col.f32.bf16.bf16.f32 "
        "{%0,%1,%2,%3}, {%4,%5,%6,%7}, {%8,%9}, {%0,%1,%2,%3};"
        : "+f"(d[0]), "+f"(d[1]), "+f"(d[2]), "+f"(d[3])
        : "r"(a[0]), "r"(a[1]), "r"(a[2]), "r"(a[3]),
          "r"(b[0]), "r"(b[1]));
}

__device__ __forceinline__ void ldsm_x4(uint32_t& r0, uint32_t& r1,
                                        uint32_t& r2, uint32_t& r3,
                                        uint32_t addr) {
    asm volatile(
        "ldmatrix.sync.aligned.m8n8.x4.shared.b16 {%0,%1,%2,%3}, [%4];"
        : "=r"(r0), "=r"(r1), "=r"(r2), "=r"(r3) : "r"(addr));
}

__device__ __forceinline__ void split2(float2 v, uint32_t& hi, uint32_t& lo) {
    __nv_bfloat162 h = __floats2bfloat162_rn(v.x, v.y);
    float2 hf = __bfloat1622float2(h);
    __nv_bfloat162 l = __floats2bfloat162_rn(v.x - hf.x, v.y - hf.y);
    hi = *reinterpret_cast<uint32_t*>(&h);
    lo = *reinterpret_cast<uint32_t*>(&l);
}

// ---------------------------------------------------------------------------
// Kernel 1: weight prep — hi/lo split + inverse row norms
// ---------------------------------------------------------------------------
__global__ void prep_weight(const float* __restrict__ w) {
    int row = blockIdx.x;
    int t   = threadIdx.x;

    float4 v = reinterpret_cast<const float4*>(w)[row * 128 + t];
    float ssq = v.x * v.x + v.y * v.y + v.z * v.z + v.w * v.w;

    uint32_t h0, l0, h1, l1;
    split2(make_float2(v.x, v.y), h0, l0);
    split2(make_float2(v.z, v.w), h1, l1);

    *reinterpret_cast<uint2*>(&g_w_hi[row * KDIM + t * 4]) = make_uint2(h0, h1);
    *reinterpret_cast<uint2*>(&g_w_lo[row * KDIM + t * 4]) = make_uint2(l0, l1);

    #pragma unroll
    for (int off = 16; off > 0; off >>= 1)
        ssq += __shfl_xor_sync(0xFFFFFFFFu, ssq, off);

    __shared__ float ws[4];
    if ((t & 31) == 0) ws[t >> 5] = ssq;
    __syncthreads();
    if (t == 0) {
        float s = ws[0] + ws[1] + ws[2] + ws[3];
        g_wninv[row] = 1.0f / fmaxf(sqrtf(s), 1e-12f);
    }
}

// ---------------------------------------------------------------------------
// Kernel 2: fused bf16-split GEMM + bcos epilogue
// ---------------------------------------------------------------------------
__global__ void __launch_bounds__(NTHREADS, 1)
bcos_gemm(const float* __restrict__ z, float* __restrict__ out, int M) {
    extern __shared__ char smem[];
    uint32_t sb = smem_u32(smem);
    int tid = threadIdx.x;
    int wid = tid >> 5, lid = tid & 31;
    int mw = wid >> 2, nw = wid & 3;       // warp grid 2(m) x 4(n)
    int mbase = mw * 64, nbase = nw * 64;  // warp tile 64x64
    int g = lid >> 2, q = lid & 3;

    int tm = blockIdx.x >> 1, tn = blockIdx.x & 1;
    int m0 = tm * TM, n0 = tn * TN;

    reinterpret_cast<float*>(smem + S_WNI)[tid] = g_wninv[n0 + tid];

    float acc[4][8][4];
    #pragma unroll
    for (int a = 0; a < 4; a++)
        #pragma unroll
        for (int b = 0; b < 8; b++)
            #pragma unroll
            for (int c = 0; c < 4; c++) acc[a][b][c] = 0.0f;
    float ssq = 0.0f;

    auto copyA = [&](int c, int s) {
        int k0 = c * KC;
        #pragma unroll
        for (int i = 0; i < 8; i++) {
            int id = tid + i * NTHREADS;          // 16B units
            int row = id >> 4, c16 = id & 15;
            int grow = m0 + row;
            const float* src = z + (size_t)(grow < M ? grow : 0) * KDIM + k0 + c16 * 4;
            uint32_t dst = sb + S_AF32 + s * 32768 + row * 256 + ((c16 ^ (row & 15)) << 4);
            int sz = (grow < M) ? 16 : 0;
            asm volatile("cp.async.cg.shared.global [%0], [%1], 16, %2;"
                         :: "r"(dst), "l"(src), "r"(sz));
        }
    };
    auto copyB = [&](int c, int s) {
        int k0 = c * KC;
        #pragma unroll
        for (int i = 0; i < 16; i++) {
            int id = tid + i * NTHREADS;
            int part = id >> 11, rid = id & 2047;
            int row = rid >> 3, c16 = rid & 7;
            const __nv_bfloat16* base = part ? g_w_lo : g_w_hi;
            const __nv_bfloat16* src = base + (size_t)(n0 + row) * KDIM + k0 + c16 * 8;
            uint32_t dst = sb + S_B + s * 65536 + part * 32768
                         + row * 128 + ((c16 * 16) ^ ((row & 7) * 16));
            asm volatile("cp.async.cg.shared.global [%0], [%1], 16;"
                         :: "r"(dst), "l"(src));
        }
    };

    copyA(0, 0); copyB(0, 0);
    asm volatile("cp.async.commit_group;");
    copyA(1, 1); copyB(1, 1);
    asm volatile("cp.async.commit_group;");

    int lr = lid & 7, sg = lid >> 3;       // ldmatrix lane mapping
    int lt = sg;                           // alias for B path

    for (int c = 0; c < NCHUNKS; c++) {
        int s = c & 1;
        if (c < NCHUNKS - 1) asm volatile("cp.async.wait_group 1;");
        else                 asm volatile("cp.async.wait_group 0;");
        __syncthreads();   // A-f32(c), B(c) landed; prev MMAs done -> ABF writable

        // ---- convert pass: fp32 A tile -> bf16 hi/lo SMEM, fused ssq
        {
            const char* Af = smem + S_AF32 + s * 32768;
            int row = tid >> 1, h = tid & 1;
            #pragma unroll
            for (int j = 0; j < 8; j++) {
                int c16 = h * 8 + j;
                uint4 v = *reinterpret_cast<const uint4*>(
                    Af + row * 256 + ((c16 ^ (row & 15)) << 4));
                float x0 = __uint_as_float(v.x), x1 = __uint_as_float(v.y);
                float x2 = __uint_as_float(v.z), x3 = __uint_as_float(v.w);
                ssq += x0 * x0 + x1 * x1 + x2 * x2 + x3 * x3;
                uint32_t h0, l0, h1, l1;
                split2(make_float2(x0, x1), h0, l0);
                split2(make_float2(x2, x3), h1, l1);
                uint32_t co = (uint32_t)(c16 * 8) ^ ((row & 7) << 4);
                *reinterpret_cast<uint2*>(smem + S_ABF + row * 128 + co) =
                    make_uint2(h0, h1);
                *reinterpret_cast<uint2*>(smem + S_ABF + 16384 + row * 128 + co) =
                    make_uint2(l0, l1);
            }
        }
        __syncthreads();   // ABF visible

        uint32_t Bbase = sb + S_B + s * 65536;

        #pragma unroll
        for (int ks = 0; ks < 4; ks++) {
            int k16 = ks * 16;

            // ---- A fragments via ldmatrix (hi + lo)
            uint32_t ahi[4][4], alo[4][4];
            int acol = k16 + (sg >> 1) * 8;
            #pragma unroll
            for (int mt = 0; mt < 4; mt++) {
                int ar = mbase + mt * 16 + lr + (sg & 1) * 8;
                uint32_t addr = sb + S_ABF + ar * 128
                              + (((uint32_t)(acol * 2)) ^ ((ar & 7) << 4));
                ldsm_x4(ahi[mt][0], ahi[mt][1], ahi[mt][2], ahi[mt][3], addr);
                ldsm_x4(alo[mt][0], alo[mt][1], alo[mt][2], alo[mt][3],
                        addr + 16384);
            }

            // ---- B fragments + MMAs in two nt-halves (reg pressure)
            #pragma unroll
            for (int half = 0; half < 2; half++) {
                uint32_t bhi[4][2], blo[4][2];
                #pragma unroll
                for (int jj = 0; jj < 2; jj++) {
                    int j = (half * 2 + jj) * 2 + (lt >> 1);
                    int kk = k16 + (lt & 1) * 8;
                    int row = nbase + j * 8 + lr;
                    uint32_t a0 = Bbase + row * 128 + ((kk * 2) ^ ((row & 7) * 16));
                    ldsm_x4(bhi[jj * 2][0], bhi[jj * 2][1],
                            bhi[jj * 2 + 1][0], bhi[jj * 2 + 1][1], a0);
                    ldsm_x4(blo[jj * 2][0], blo[jj * 2][1],
                            blo[jj * 2 + 1][0], blo[jj * 2 + 1][1], a0 + 32768);
                }
                #pragma unroll
                for (int mt = 0; mt < 4; mt++)
                    #pragma unroll
                    for (int nt = 0; nt < 4; nt++) {
                        float* d = acc[mt][half * 4 + nt];
                        mma_bf16(d, ahi[mt], bhi[nt]);
                        mma_bf16(d, ahi[mt], blo[nt]);
                        mma_bf16(d, alo[mt], bhi[nt]);
                    }
            }
        }

        __syncthreads();   // all warps done reading stage s
        if (c + 2 < NCHUNKS) {
            copyA(c + 2, s); copyB(c + 2, s);
            asm volatile("cp.async.commit_group;");
        }
    }

    // ---- publish inverse z-norms (2 threads per row)
    ssq += __shfl_xor_sync(0xFFFFFFFFu, ssq, 1);
    if ((tid & 1) == 0)
        reinterpret_cast<float*>(smem + S_ZS)[tid >> 1] =
            1.0f / fmaxf(sqrtf(ssq), 1e-12f);
    __syncthreads();

    // ---- epilogue
    const float* zs  = reinterpret_cast<const float*>(smem + S_ZS);
    const float* wni = reinterpret_cast<const float*>(smem + S_WNI);

    #pragma unroll
    for (int mt = 0; mt < 4; mt++) {
        int r0 = mbase + mt * 16 + g;
        float iz0 = zs[r0], iz1 = zs[r0 + 8];
        int gr0 = m0 + r0;
        bool ok0 = (gr0 < M), ok1 = (gr0 + 8 < M);
        float* op0 = out + (size_t)gr0 * NDIM + n0;
        float* op1 = op0 + (size_t)8 * NDIM;
        #pragma unroll
        for (int nt = 0; nt < 8; nt++) {
            int cb = nbase + nt * 8 + 2 * q;
            float w0 = wni[cb], w1 = wni[cb + 1];
            if (ok0) {
                float v0 = acc[mt][nt][0], v1 = acc[mt][nt][1];
                float2 o;
                o.x = v0 * fabsf(v0) * iz0 * w0;
                o.y = v1 * fabsf(v1) * iz0 * w1;
                *reinterpret_cast<float2*>(op0 + cb) = o;
            }
            if (ok1) {
                float v2 = acc[mt][nt][2], v3 = acc[mt][nt][3];
                float2 o;
                o.x = v2 * fabsf(v2) * iz1 * w0;
                o.y = v3 * fabsf(v3) * iz1 * w1;
                *reinterpret_cast<float2*>(op1 + cb) = o;
            }
        }
    }
}

// ---------------------------------------------------------------------------
extern "C" void kernel_launch(void* const* d_in, const int* in_sizes, int n_in,
                              void* d_out, int out_size) {
    const float* z = (const float*)d_in[0];
    const float* w = (const float*)d_in[1];
    float* out = (float*)d_out;
    int M = in_sizes[0] / KDIM;

    cudaFuncSetAttribute(bcos_gemm,
                         cudaFuncAttributeMaxDynamicSharedMemorySize, S_TOTAL);

    prep_weight<<<NDIM, 128>>>(w);

    int tiles_m = (M + TM - 1) / TM;
    bcos_gemm<<<tiles_m * 2, NTHREADS, S_TOTAL>>>(z, out, M);
}